// round 6
// baseline (speedup 1.0000x reference)
#include <cuda_runtime.h>
#include <cuda_fp16.h>
#include <cstdint>

// Problem constants (fixed by the dataset)
#define N_NODES 10000
#define N_EDGES 320000
#define D_FEAT  128
#define OUT_DIM 128
#define SCALES  3
#define KDIM    384
#define NTILES  (N_EDGES / 128)   // 2500

// ---------------------------------------------------------------------------
// Device globals
// ---------------------------------------------------------------------------
__device__ __align__(16) float g_NA[N_NODES * KDIM];
__device__ __align__(16) float g_NB[N_NODES * KDIM];
__device__ __align__(16) float g_b2m[128];
__device__ __align__(16) float c_W1g[SCALES * 128];
__device__ __align__(16) float c_b1g[SCALES * 128];
__device__ int g_idx64;

// ---------------------------------------------------------------------------
// Baseline-PTX helpers (compile for plain sm_103)
// ---------------------------------------------------------------------------
__device__ __forceinline__ uint32_t smem_to_u32(const void* p) {
    uint32_t a;
    asm("{ .reg .u64 t; cvta.to.shared.u64 t, %1; cvt.u32.u64 %0, t; }" : "=r"(a) : "l"(p));
    return a;
}

#define LDSM_X4(r, addr) \
    asm volatile("ldmatrix.sync.aligned.m8n8.x4.shared.b16 {%0,%1,%2,%3}, [%4];" \
        : "=r"((r)[0]), "=r"((r)[1]), "=r"((r)[2]), "=r"((r)[3]) : "r"(addr))

#define LDSM_X4T(r, addr) \
    asm volatile("ldmatrix.sync.aligned.m8n8.x4.trans.shared.b16 {%0,%1,%2,%3}, [%4];" \
        : "=r"((r)[0]), "=r"((r)[1]), "=r"((r)[2]), "=r"((r)[3]) : "r"(addr))

__device__ __forceinline__ void mma_f16(float c[4], const uint32_t a[4],
                                        uint32_t b0, uint32_t b1) {
    asm volatile(
        "mma.sync.aligned.m16n8k16.row.col.f32.f16.f16.f32 "
        "{%0,%1,%2,%3}, {%4,%5,%6,%7}, {%8,%9}, {%0,%1,%2,%3};"
        : "+f"(c[0]), "+f"(c[1]), "+f"(c[2]), "+f"(c[3])
        : "r"(a[0]), "r"(a[1]), "r"(a[2]), "r"(a[3]), "r"(b0), "r"(b1));
}

__device__ __forceinline__ uint32_t pack_h2(float lo, float hi) {
    __half2 h = __floats2half2_rn(lo, hi);
    return *(uint32_t*)&h;
}

// ---------------------------------------------------------------------------
// Kernel 0: edge_index dtype detection (JAX x64-off silently gives int32).
// ---------------------------------------------------------------------------
__global__ void detect_idx_kernel(const int* __restrict__ ei_raw) {
    int t = threadIdx.x;  // 128 threads
    int nz = (ei_raw[2 * t + 1] != 0) ? 1 : 0;
    int tot = __syncthreads_count(nz);
    if (t == 0) g_idx64 = (tot == 0) ? 1 : 0;
}

// ---------------------------------------------------------------------------
// Kernel 0b: stage tile-invariant layer-1 rows (gap weight G, b1) + mean b2.
// ---------------------------------------------------------------------------
__global__ void stage_small_kernel(const float* __restrict__ W1,
                                   const float* __restrict__ b1,
                                   const float* __restrict__ b2) {
    int t = blockIdx.x * 128 + threadIdx.x;   // 0..383
    if (t < SCALES * 128) {
        int s = t >> 7, n = t & 127;
        c_W1g[t] = W1[s * (257 * 128) + 256 * 128 + n];
        c_b1g[t] = b1[t];
    }
    if (t < 128) {
        g_b2m[t] = (b2[t] + b2[128 + t] + b2[256 + t]) * (1.0f / 3.0f);
    }
}

// ---------------------------------------------------------------------------
// Kernel 1: node precompute GEMM (exact fp32).
// ---------------------------------------------------------------------------
__global__ __launch_bounds__(256, 1)
void node_pre_kernel(const float* __restrict__ nf,
                     const float* __restrict__ W1) {
    extern __shared__ float sm1[];
    float* As = sm1;              // [128][68]
    float* Bs = sm1 + 128 * 68;   // [128][128]

    const int tid  = threadIdx.x;
    const int c    = blockIdx.y;
    const int s    = c % 3;
    const int part = c / 3;
    const int n0   = blockIdx.x * 64;

    const float* Wbase = W1 + s * (257 * 128) + part * (128 * 128);
    {
        const float4* w4 = (const float4*)Wbase;
        float4* b4 = (float4*)Bs;
        #pragma unroll
        for (int i = 0; i < 16; i++) b4[tid + i * 256] = w4[tid + i * 256];
    }
    {
        #pragma unroll
        for (int i = 0; i < 8; i++) {
            int idx = tid + i * 256;
            int m   = idx >> 5;
            int k4  = idx & 31;
            float4 v = make_float4(0.f, 0.f, 0.f, 0.f);
            if (n0 + m < N_NODES) v = ((const float4*)nf)[(n0 + m) * 32 + k4];
            As[(k4 * 4 + 0) * 68 + m] = v.x;
            As[(k4 * 4 + 1) * 68 + m] = v.y;
            As[(k4 * 4 + 2) * 68 + m] = v.z;
            As[(k4 * 4 + 3) * 68 + m] = v.w;
        }
    }
    __syncthreads();

    const int tm = tid >> 4;
    const int tn = tid & 15;
    float acc[4][8];
    #pragma unroll
    for (int i = 0; i < 4; i++)
        #pragma unroll
        for (int j = 0; j < 8; j++) acc[i][j] = 0.f;

    #pragma unroll 8
    for (int k = 0; k < 128; k++) {
        float4 a4  = *(const float4*)&As[k * 68 + tm * 4];
        float4 bb0 = *(const float4*)&Bs[k * 128 + tn * 8];
        float4 bb1 = *(const float4*)&Bs[k * 128 + tn * 8 + 4];
        float a[4] = {a4.x, a4.y, a4.z, a4.w};
        float b[8] = {bb0.x, bb0.y, bb0.z, bb0.w, bb1.x, bb1.y, bb1.z, bb1.w};
        #pragma unroll
        for (int i = 0; i < 4; i++)
            #pragma unroll
            for (int j = 0; j < 8; j++) acc[i][j] += a[i] * b[j];
    }

    float* outg = part ? g_NB : g_NA;
    #pragma unroll
    for (int i = 0; i < 4; i++) {
        int n_node = n0 + tm * 4 + i;
        if (n_node < N_NODES) {
            float* dst = outg + n_node * KDIM + s * 128 + tn * 8;
            *(float4*)dst       = make_float4(acc[i][0], acc[i][1], acc[i][2], acc[i][3]);
            *(float4*)(dst + 4) = make_float4(acc[i][4], acc[i][5], acc[i][6], acc[i][7]);
        }
    }
}

// ---------------------------------------------------------------------------
// Kernel 2: persistent fp16 mma.sync edge kernel, ldmatrix fragments.
// grid=148 x 512 threads (16 warps). Warp wid: m-rows [(wid>>1)*16, +16),
// n-cols [(wid&1)*64, +64). Per 128-edge tile: build full H (128 x 384 fp16,
// all 3 scales) once, 1 sync, then 24 k16-steps of MMAs with no syncs.
// W2 (fp16, row = global k, 272B stride) staged once per CTA.
// ---------------------------------------------------------------------------
#define W2_ROWB  272                     // 128 fp16 (256B) + 16B pad
#define H_ROWB   784                     // 384 fp16 (768B) + 16B pad
#define SMEM_W2  0                       // 384*272 = 104448
#define SMEM_H   104448                  // 128*784 = 100352
#define SMEM_SRC 204800
#define SMEM_DST 205312
#define SMEM_GAP 205824
#define SMEM_TOT 206336

__global__ __launch_bounds__(512, 1)
void edge_kernel(const float* __restrict__ temporal,
                 const float* __restrict__ W2,
                 const void* __restrict__ ei,
                 float* __restrict__ out) {
    extern __shared__ char smem[];
    const uint32_t smem_u = smem_to_u32(smem);
    const uint32_t W2u = smem_u + SMEM_W2;
    const uint32_t Hu  = smem_u + SMEM_H;

    int*   s_src = (int*)(smem + SMEM_SRC);
    int*   s_dst = (int*)(smem + SMEM_DST);
    float* s_gap = (float*)(smem + SMEM_GAP);

    const int tid  = threadIdx.x;
    const int wid  = tid >> 5;
    const int lane = tid & 31;
    const int gid  = lane >> 2;
    const int qid  = lane & 3;
    const int m0   = (wid >> 1) * 16;     // 8 m-groups of 16 rows
    const int ncol0 = (wid & 1) * 64;     // 2 n-halves
    const int row  = tid >> 2;            // H-build: edge row
    const int q    = tid & 3;             // H-build: 32-k quarter within scale

    // Stage W2 -> fp16 smem once. Row = global k (s*128+k), 128 fp16 + pad.
    for (int i = tid; i < 384 * 64; i += 512) {
        int krow = i >> 6;
        int np   = i & 63;
        float2 v = *(const float2*)(W2 + krow * 128 + np * 2);
        *(uint32_t*)(smem + SMEM_W2 + krow * W2_ROWB + np * 4) = pack_h2(v.x, v.y);
    }

    // Per-lane ldmatrix base offsets.
    const int g = lane >> 3, r = lane & 7;
    // A tiles: group g -> (m-half g&1, k-half g>>1). addr = H[m0+(g&1)*8+r][kstep*16+(g>>1)*8]
    const uint32_t a_lane = Hu + (uint32_t)((m0 + (g & 1) * 8 + r) * H_ROWB + (g >> 1) * 16);
    // B tiles: group g -> (k-half g&1, n-pair-half g>>1). addr = W2[k0+(g&1)*8+r][ncol0+np*16+(g>>1)*8]
    const uint32_t b_lane = W2u + (uint32_t)(((g & 1) * 8 + r) * W2_ROWB + (ncol0 + (g >> 1) * 8) * 2);

    const int idx64 = g_idx64;
    const float inv3 = 1.0f / 3.0f;

    __syncthreads();

    for (int tt = blockIdx.x; tt < NTILES; tt += gridDim.x) {
        const int e0 = tt * 128;
        if (tid < 128) {
            int si, di;
            if (idx64) {
                si = (int)((const long long*)ei)[e0 + tid];
                di = (int)((const long long*)ei)[N_EDGES + e0 + tid];
            } else {
                si = ((const int*)ei)[e0 + tid];
                di = ((const int*)ei)[N_EDGES + e0 + tid];
            }
            s_src[tid] = si; s_dst[tid] = di;
            s_gap[tid] = temporal[si] - temporal[di];
        }
        __syncthreads();

        // ---- Build full H tile: 128 rows x 384 fp16 (3 scales) ----
        {
            const int   src_n = s_src[row];
            const int   dst_n = s_dst[row];
            const float gap   = s_gap[row];
            #pragma unroll
            for (int s = 0; s < SCALES; s++) {
                const float4* naP = (const float4*)g_NA + (size_t)src_n * 96 + s * 32 + q * 8;
                const float4* nbP = (const float4*)g_NB + (size_t)dst_n * 96 + s * 32 + q * 8;
                const float4* gP  = (const float4*)(c_W1g + s * 128) + q * 8;
                const float4* bP  = (const float4*)(c_b1g + s * 128) + q * 8;
                char* dstb = smem + SMEM_H + row * H_ROWB + s * 256 + q * 64;
                #pragma unroll
                for (int i2 = 0; i2 < 4; i2++) {
                    float4 na0 = naP[2 * i2],     nb0 = nbP[2 * i2];
                    float4 gg0 = gP[2 * i2],      bb0 = bP[2 * i2];
                    float4 na1 = naP[2 * i2 + 1], nb1 = nbP[2 * i2 + 1];
                    float4 gg1 = gP[2 * i2 + 1],  bb1 = bP[2 * i2 + 1];
                    uint4 hv;
                    hv.x = pack_h2(fmaxf(na0.x + nb0.x + gap * gg0.x + bb0.x, 0.f),
                                   fmaxf(na0.y + nb0.y + gap * gg0.y + bb0.y, 0.f));
                    hv.y = pack_h2(fmaxf(na0.z + nb0.z + gap * gg0.z + bb0.z, 0.f),
                                   fmaxf(na0.w + nb0.w + gap * gg0.w + bb0.w, 0.f));
                    hv.z = pack_h2(fmaxf(na1.x + nb1.x + gap * gg1.x + bb1.x, 0.f),
                                   fmaxf(na1.y + nb1.y + gap * gg1.y + bb1.y, 0.f));
                    hv.w = pack_h2(fmaxf(na1.z + nb1.z + gap * gg1.z + bb1.z, 0.f),
                                   fmaxf(na1.w + nb1.w + gap * gg1.w + bb1.w, 0.f));
                    *(uint4*)(dstb + i2 * 16) = hv;
                }
            }
        }
        __syncthreads();

        // ---- MMA phase: 24 k16-steps, no syncs ----
        float acc[8][4];
        #pragma unroll
        for (int nf = 0; nf < 8; nf++)
            #pragma unroll
            for (int k = 0; k < 4; k++) acc[nf][k] = 0.f;

        #pragma unroll
        for (int s = 0; s < SCALES; s++) {
            const uint32_t abase = a_lane + (uint32_t)(s * 256);
            const uint32_t bbase = b_lane + (uint32_t)(s * 128 * W2_ROWB);
            #pragma unroll
            for (int ks = 0; ks < 8; ks++) {
                uint32_t a[4];
                LDSM_X4(a, abase + (uint32_t)(ks * 32));
                #pragma unroll
                for (int np = 0; np < 4; np++) {
                    uint32_t b[4];
                    LDSM_X4T(b, bbase + (uint32_t)(ks * 16 * W2_ROWB + np * 32));
                    mma_f16(acc[np * 2],     a, b[0], b[1]);
                    mma_f16(acc[np * 2 + 1], a, b[2], b[3]);
                }
            }
        }

        // ---- Epilogue: out = acc/3 + mean(b2) ----
        {
            const size_t r0 = (size_t)(e0 + m0 + gid);
            #pragma unroll
            for (int nf = 0; nf < 8; nf++) {
                int col = ncol0 + nf * 8 + qid * 2;
                float2 bm = *(const float2*)(g_b2m + col);
                *(float2*)(out + r0 * 128 + col) =
                    make_float2(acc[nf][0] * inv3 + bm.x, acc[nf][1] * inv3 + bm.y);
                *(float2*)(out + (r0 + 8) * 128 + col) =
                    make_float2(acc[nf][2] * inv3 + bm.x, acc[nf][3] * inv3 + bm.y);
            }
        }
        __syncthreads();
    }
}

// ---------------------------------------------------------------------------
// Launch
// ---------------------------------------------------------------------------
extern "C" void kernel_launch(void* const* d_in, const int* in_sizes, int n_in,
                              void* d_out, int out_size) {
    const float* nf = 0;
    const float* temporal = 0;
    const float* W1 = 0;
    const float* b1 = 0;
    const float* W2 = 0;
    const float* b2 = 0;
    const void*  ei = 0;

    for (int i = 0; i < n_in; i++) {
        switch (in_sizes[i]) {
            case N_NODES * D_FEAT:   nf = (const float*)d_in[i]; break;
            case N_NODES:            temporal = (const float*)d_in[i]; break;
            case SCALES * 257 * 128: W1 = (const float*)d_in[i]; break;
            case SCALES * 128 * 128: W2 = (const float*)d_in[i]; break;
            case 2 * N_EDGES:        ei = d_in[i]; break;
            case SCALES * 128:
                if (!b1) b1 = (const float*)d_in[i];
                else     b2 = (const float*)d_in[i];
                break;
            default: break;
        }
    }
    float* out = (float*)d_out;

    const int smem1 = (128 * 68 + 128 * 128) * sizeof(float);
    cudaFuncSetAttribute(node_pre_kernel, cudaFuncAttributeMaxDynamicSharedMemorySize, smem1);
    cudaFuncSetAttribute(edge_kernel,     cudaFuncAttributeMaxDynamicSharedMemorySize, SMEM_TOT);

    detect_idx_kernel<<<1, 128>>>((const int*)ei);
    stage_small_kernel<<<3, 128>>>(W1, b1, b2);

    dim3 g1((N_NODES + 63) / 64, 6);
    node_pre_kernel<<<g1, 256, smem1>>>(nf, W1);

    edge_kernel<<<148, 512, SMEM_TOT>>>(temporal, W2, ei, out);
}

// round 7
// speedup vs baseline: 2.4899x; 2.4899x over previous
#include <cuda_runtime.h>
#include <cuda_fp16.h>
#include <cstdint>

// Problem constants (fixed by the dataset)
#define N_NODES 10000
#define N_EDGES 320000
#define D_FEAT  128
#define OUT_DIM 128
#define SCALES  3
#define KDIM    384
#define NTILES  (N_EDGES / 128)   // 2500

// ---------------------------------------------------------------------------
// Device globals
// ---------------------------------------------------------------------------
// Layer-1 node partials in fp16 (half2-packed): [node][192 u32] = 384 halfs.
__device__ __align__(16) uint32_t g_NAh[N_NODES * 192];
__device__ __align__(16) uint32_t g_NBh[N_NODES * 192];
// W2 pre-packed k-pair image: row r = s*64+kp (kp = k/2), 136 words/row
// (128 data + 8 pad). word(r, n) = half2(W2[s][2kp][n], W2[s][2kp+1][n]).
__device__ __align__(16) uint32_t g_W2kp[192 * 136];
__device__ __align__(16) float g_b2m[128];
__device__ __align__(16) float c_W1g[SCALES * 128];
__device__ __align__(16) float c_b1g[SCALES * 128];
__device__ int g_idx64;

// ---------------------------------------------------------------------------
// Baseline-PTX helpers (compile for plain sm_103)
// ---------------------------------------------------------------------------
__device__ __forceinline__ uint32_t smem_to_u32(const void* p) {
    uint32_t a;
    asm("{ .reg .u64 t; cvta.to.shared.u64 t, %1; cvt.u32.u64 %0, t; }" : "=r"(a) : "l"(p));
    return a;
}

#define LDSM_X4(r, addr) \
    asm volatile("ldmatrix.sync.aligned.m8n8.x4.shared.b16 {%0,%1,%2,%3}, [%4];" \
        : "=r"((r)[0]), "=r"((r)[1]), "=r"((r)[2]), "=r"((r)[3]) : "r"(addr))

__device__ __forceinline__ void mma_f16(float c[4], const uint32_t a[4],
                                        uint32_t b0, uint32_t b1) {
    asm volatile(
        "mma.sync.aligned.m16n8k16.row.col.f32.f16.f16.f32 "
        "{%0,%1,%2,%3}, {%4,%5,%6,%7}, {%8,%9}, {%0,%1,%2,%3};"
        : "+f"(c[0]), "+f"(c[1]), "+f"(c[2]), "+f"(c[3])
        : "r"(a[0]), "r"(a[1]), "r"(a[2]), "r"(a[3]), "r"(b0), "r"(b1));
}

__device__ __forceinline__ uint32_t pack_h2(float lo, float hi) {
    __half2 h = __floats2half2_rn(lo, hi);
    return *(uint32_t*)&h;
}
__device__ __forceinline__ float2 h2f2(uint32_t w) {
    return __half22float2(*(__half2*)&w);
}

// ---------------------------------------------------------------------------
// Kernel 0: edge_index dtype detection (JAX x64-off silently gives int32).
// ---------------------------------------------------------------------------
__global__ void detect_idx_kernel(const int* __restrict__ ei_raw) {
    int t = threadIdx.x;  // 128 threads
    int nz = (ei_raw[2 * t + 1] != 0) ? 1 : 0;
    int tot = __syncthreads_count(nz);
    if (t == 0) g_idx64 = (tot == 0) ? 1 : 0;
}

// ---------------------------------------------------------------------------
// Kernel 0b: W2 k-pair fp16 image + mean bias.
// ---------------------------------------------------------------------------
__global__ void w2prep_kernel(const float* __restrict__ W2,
                              const float* __restrict__ b2) {
    int id = blockIdx.x * 256 + threadIdx.x;     // word index, 0..26111
    if (id < 192 * 136) {
        int r = id / 136, n = id - r * 136;
        int s = r >> 6, kp = r & 63;
        uint32_t v = 0;
        if (n < 128) {
            float lo = W2[(s * 128 + 2 * kp) * 128 + n];
            float hi = W2[(s * 128 + 2 * kp + 1) * 128 + n];
            v = pack_h2(lo, hi);
        }
        g_W2kp[id] = v;
    }
    if (blockIdx.x == 0 && threadIdx.x < 128) {
        int n = threadIdx.x;
        g_b2m[n] = (b2[n] + b2[128 + n] + b2[256 + n]) * (1.0f / 3.0f);
    }
}

// ---------------------------------------------------------------------------
// Kernel 0c: stage tile-invariant layer-1 rows (gap weight G, b1).
// ---------------------------------------------------------------------------
__global__ void stage_small_kernel(const float* __restrict__ W1,
                                   const float* __restrict__ b1) {
    int t = blockIdx.x * 128 + threadIdx.x;   // 0..383
    if (t < SCALES * 128) {
        int s = t >> 7, n = t & 127;
        c_W1g[t] = W1[s * (257 * 128) + 256 * 128 + n];
        c_b1g[t] = b1[t];
    }
}

// ---------------------------------------------------------------------------
// Kernel 1: node precompute GEMM (fp32 compute, fp16 output).
// ---------------------------------------------------------------------------
__global__ __launch_bounds__(256, 1)
void node_pre_kernel(const float* __restrict__ nf,
                     const float* __restrict__ W1) {
    extern __shared__ float sm1[];
    float* As = sm1;              // [128][68]
    float* Bs = sm1 + 128 * 68;   // [128][128]

    const int tid  = threadIdx.x;
    const int c    = blockIdx.y;
    const int s    = c % 3;
    const int part = c / 3;
    const int n0   = blockIdx.x * 64;

    const float* Wbase = W1 + s * (257 * 128) + part * (128 * 128);
    {
        const float4* w4 = (const float4*)Wbase;
        float4* b4 = (float4*)Bs;
        #pragma unroll
        for (int i = 0; i < 16; i++) b4[tid + i * 256] = w4[tid + i * 256];
    }
    {
        #pragma unroll
        for (int i = 0; i < 8; i++) {
            int idx = tid + i * 256;
            int m   = idx >> 5;
            int k4  = idx & 31;
            float4 v = make_float4(0.f, 0.f, 0.f, 0.f);
            if (n0 + m < N_NODES) v = ((const float4*)nf)[(n0 + m) * 32 + k4];
            As[(k4 * 4 + 0) * 68 + m] = v.x;
            As[(k4 * 4 + 1) * 68 + m] = v.y;
            As[(k4 * 4 + 2) * 68 + m] = v.z;
            As[(k4 * 4 + 3) * 68 + m] = v.w;
        }
    }
    __syncthreads();

    const int tm = tid >> 4;
    const int tn = tid & 15;
    float acc[4][8];
    #pragma unroll
    for (int i = 0; i < 4; i++)
        #pragma unroll
        for (int j = 0; j < 8; j++) acc[i][j] = 0.f;

    #pragma unroll 8
    for (int k = 0; k < 128; k++) {
        float4 a4  = *(const float4*)&As[k * 68 + tm * 4];
        float4 bb0 = *(const float4*)&Bs[k * 128 + tn * 8];
        float4 bb1 = *(const float4*)&Bs[k * 128 + tn * 8 + 4];
        float a[4] = {a4.x, a4.y, a4.z, a4.w};
        float b[8] = {bb0.x, bb0.y, bb0.z, bb0.w, bb1.x, bb1.y, bb1.z, bb1.w};
        #pragma unroll
        for (int i = 0; i < 4; i++)
            #pragma unroll
            for (int j = 0; j < 8; j++) acc[i][j] += a[i] * b[j];
    }

    uint32_t* outg = part ? g_NBh : g_NAh;
    #pragma unroll
    for (int i = 0; i < 4; i++) {
        int n_node = n0 + tm * 4 + i;
        if (n_node < N_NODES) {
            uint4 v;
            v.x = pack_h2(acc[i][0], acc[i][1]);
            v.y = pack_h2(acc[i][2], acc[i][3]);
            v.z = pack_h2(acc[i][4], acc[i][5]);
            v.w = pack_h2(acc[i][6], acc[i][7]);
            *(uint4*)(outg + (size_t)n_node * 192 + s * 64 + tn * 4) = v;
        }
    }
}

// ---------------------------------------------------------------------------
// Kernel 2: warp-specialized fp16 mma edge kernel.
// 512 threads: warps 0-7 consumers (MMA, warp tile m32 x n64),
// warps 8-15 producers (coalesced gather + H build).
// Phases j = 3*tile + scale; producers fill Hbuf[j&1] while consumers
// process phase j-1 from Hbuf[(j-1)&1]; one __syncthreads per phase.
// H row stride 272B (68w = 4 mod 32: ldmatrix conflict-free);
// W2kp row stride 136w (= 8 mod 32: scalar B loads conflict-free).
// ---------------------------------------------------------------------------
#define H_ROWB   272
#define SMEM_W2  0                 // 192*136*4 = 104448
#define SMEM_H0  104448            // 128*272 = 34816
#define SMEM_H1  139264
#define SMEM_TOT 174080

__global__ __launch_bounds__(512, 1)
void edge_kernel(const float* __restrict__ temporal,
                 const void* __restrict__ ei,
                 float* __restrict__ out) {
    extern __shared__ char smem[];
    const uint32_t smem_u = smem_to_u32(smem);
    const uint32_t* W2w = (const uint32_t*)smem;   // word-indexed smem

    const int tid  = threadIdx.x;
    const int wid  = tid >> 5;
    const int lane = tid & 31;
    const int gid  = lane >> 2;
    const int qid  = lane & 3;
    const int role = wid >> 3;                     // 0 = consumer, 1 = producer

    // Stage W2kp image into smem once.
    {
        const uint4* src = (const uint4*)g_W2kp;
        uint4* dst = (uint4*)(smem + SMEM_W2);
        for (int i = tid; i < 192 * 136 / 4; i += 512) dst[i] = src[i];
    }
    __syncthreads();

    // Consumer constants
    const int m0   = (wid >> 1) * 32;              // consumer: 4 m-groups
    const int nc0  = (wid & 1) * 64;               // consumer: 2 n-halves
    const int arow = m0 + (lane & 7) + 8 * ((lane >> 3) & 1);
    const uint32_t acb = (uint32_t)(((lane >> 4) & 1) * 16);

    // Producer constants
    const int pw = wid - 8;                        // producer warp 0..7

    const int idx64 = g_idx64;
    const float inv3 = 1.0f / 3.0f;

    // CTA tile count
    int nt = 0;
    for (int tt = blockIdx.x; tt < NTILES; tt += 148) nt++;

    float acc[2][8][4];
    #pragma unroll
    for (int mi = 0; mi < 2; mi++)
        #pragma unroll
        for (int g = 0; g < 8; g++)
            #pragma unroll
            for (int q = 0; q < 4; q++) acc[mi][g][q] = 0.f;

    const int P = 3 * nt + 1;
    for (int j = 0; j < P; j++) {
        if (role == 1 && j < 3 * nt) {
            // ---- producer: build H for phase j ----
            const int tile = j / 3;
            const int s    = j - 3 * tile;
            const int e0   = (blockIdx.x + tile * 148) * 128;
            char* hb = smem + ((j & 1) ? SMEM_H1 : SMEM_H0);

            const float4 gv = *(const float4*)(c_W1g + s * 128 + lane * 4);
            const float4 bv = *(const float4*)(c_b1g + s * 128 + lane * 4);

            #pragma unroll 4
            for (int r = 0; r < 16; r++) {
                const int row = pw * 16 + r;
                int si, di;
                if (idx64) {
                    si = (int)((const long long*)ei)[e0 + row];
                    di = (int)((const long long*)ei)[N_EDGES + e0 + row];
                } else {
                    si = ((const int*)ei)[e0 + row];
                    di = ((const int*)ei)[N_EDGES + e0 + row];
                }
                const float gap = temporal[si] - temporal[di];
                uint2 na = *((const uint2*)(g_NAh + (size_t)si * 192 + s * 64) + lane);
                uint2 nb = *((const uint2*)(g_NBh + (size_t)di * 192 + s * 64) + lane);
                float2 a0 = h2f2(na.x), a1 = h2f2(na.y);
                float2 c0 = h2f2(nb.x), c1 = h2f2(nb.y);
                float h0 = fmaxf(a0.x + c0.x + fmaf(gap, gv.x, bv.x), 0.f);
                float h1 = fmaxf(a0.y + c0.y + fmaf(gap, gv.y, bv.y), 0.f);
                float h2 = fmaxf(a1.x + c1.x + fmaf(gap, gv.z, bv.z), 0.f);
                float h3 = fmaxf(a1.y + c1.y + fmaf(gap, gv.w, bv.w), 0.f);
                uint2 ho;
                ho.x = pack_h2(h0, h1);
                ho.y = pack_h2(h2, h3);
                *(uint2*)(hb + row * H_ROWB + lane * 8) = ho;
            }
        }
        if (role == 0 && j >= 1) {
            // ---- consumer: MMA for phase j-1 ----
            const int jj   = j - 1;
            const int tile = jj / 3;
            const int s    = jj - 3 * tile;
            const uint32_t Hb = smem_u + ((jj & 1) ? SMEM_H1 : SMEM_H0);

            #pragma unroll
            for (int ks = 0; ks < 8; ks++) {
                uint32_t a0f[4], a1f[4];
                LDSM_X4(a0f, Hb + (uint32_t)(arow * H_ROWB) + (uint32_t)(ks * 32) + acb);
                LDSM_X4(a1f, Hb + (uint32_t)((arow + 16) * H_ROWB) + (uint32_t)(ks * 32) + acb);
                const uint32_t* bp = W2w + (s * 64 + ks * 8 + qid) * 136 + nc0 + gid;
                #pragma unroll
                for (int g = 0; g < 8; g++) {
                    uint32_t b0 = bp[g * 8];
                    uint32_t b1 = bp[g * 8 + 4 * 136];
                    mma_f16(acc[0][g], a0f, b0, b1);
                    mma_f16(acc[1][g], a1f, b0, b1);
                }
            }

            if (s == 2) {
                // epilogue: out = acc/3 + mean(b2)
                const size_t e0o = (size_t)(blockIdx.x + tile * 148) * 128;
                #pragma unroll
                for (int mi = 0; mi < 2; mi++) {
                    const size_t r0 = e0o + m0 + mi * 16 + gid;
                    #pragma unroll
                    for (int g = 0; g < 8; g++) {
                        int col = nc0 + g * 8 + qid * 2;
                        float2 bm = *(const float2*)(g_b2m + col);
                        *(float2*)(out + r0 * 128 + col) =
                            make_float2(acc[mi][g][0] * inv3 + bm.x,
                                        acc[mi][g][1] * inv3 + bm.y);
                        *(float2*)(out + (r0 + 8) * 128 + col) =
                            make_float2(acc[mi][g][2] * inv3 + bm.x,
                                        acc[mi][g][3] * inv3 + bm.y);
                        #pragma unroll
                        for (int q = 0; q < 4; q++) acc[mi][g][q] = 0.f;
                    }
                }
            }
        }
        __syncthreads();
    }
}

// ---------------------------------------------------------------------------
// Launch
// ---------------------------------------------------------------------------
extern "C" void kernel_launch(void* const* d_in, const int* in_sizes, int n_in,
                              void* d_out, int out_size) {
    const float* nf = 0;
    const float* temporal = 0;
    const float* W1 = 0;
    const float* b1 = 0;
    const float* W2 = 0;
    const float* b2 = 0;
    const void*  ei = 0;

    for (int i = 0; i < n_in; i++) {
        switch (in_sizes[i]) {
            case N_NODES * D_FEAT:   nf = (const float*)d_in[i]; break;
            case N_NODES:            temporal = (const float*)d_in[i]; break;
            case SCALES * 257 * 128: W1 = (const float*)d_in[i]; break;
            case SCALES * 128 * 128: W2 = (const float*)d_in[i]; break;
            case 2 * N_EDGES:        ei = d_in[i]; break;
            case SCALES * 128:
                if (!b1) b1 = (const float*)d_in[i];
                else     b2 = (const float*)d_in[i];
                break;
            default: break;
        }
    }
    float* out = (float*)d_out;

    const int smem1 = (128 * 68 + 128 * 128) * sizeof(float);
    cudaFuncSetAttribute(node_pre_kernel, cudaFuncAttributeMaxDynamicSharedMemorySize, smem1);
    cudaFuncSetAttribute(edge_kernel,     cudaFuncAttributeMaxDynamicSharedMemorySize, SMEM_TOT);

    detect_idx_kernel<<<1, 128>>>((const int*)ei);
    w2prep_kernel<<<102, 256>>>(W2, b2);
    stage_small_kernel<<<3, 128>>>(W1, b1);

    dim3 g1((N_NODES + 63) / 64, 6);
    node_pre_kernel<<<g1, 256, smem1>>>(nf, W1);

    edge_kernel<<<148, 512, SMEM_TOT>>>(temporal, ei, out);
}